// round 5
// baseline (speedup 1.0000x reference)
#include <cuda_runtime.h>
#include <cuda_bf16.h>
#include <math.h>

// Inputs (metadata order):
//   d_in[0] predictions  float32 [B*S]  (B=1941, S=16384), row-major [B][S]
//   d_in[1] actuals      float32 [B*S]
//   d_in[2] indexes      int32   [S]
//   d_in[3] starts       int32   [N_SERIES=30490]
// Output: float32 scalar  sqrt( sum_{j,i: j>=starts[indexes[i]]} (p[j,i]-a[j,i])^2 / count )
//
// Single fused kernel:
//   grid.x = column stripes (TPB quads each; thread <-> fixed column-quad)
//   grid.y = row groups
//   Each thread gathers its 4 starts once, skips rows below min(start),
//   streams its rows, block-reduces, last block (atomicInc wrap) finalizes.

#define TPB        256
#define ROW_GROUPS 18
#define MAX_PART   2048
#define MAX_STRIPE 256

__device__ double       g_partials[MAX_PART];
__device__ long long    g_count_part[MAX_STRIPE];
__device__ unsigned int g_done;   // zero-init; atomicInc wraps -> replay-safe

__global__ __launch_bounds__(TPB)
void fused_rmse_kernel(const float4* __restrict__ p,
                       const float4* __restrict__ a,
                       const int4*   __restrict__ indexes4,
                       const int*    __restrict__ starts,
                       float* __restrict__ out,
                       int B, int S4, int rows_per_grp)
{
    const int bx  = blockIdx.x;
    const int by  = blockIdx.y;
    const int tid = threadIdx.x;
    const int c4  = bx * TPB + tid;        // this thread's column-quad
    const bool active = (c4 < S4);

    __shared__ float     shf[TPB / 32];
    __shared__ long long shc[TPB / 32];
    const int lane = tid & 31, wid = tid >> 5, nwarps = TPB >> 5;

    // ---- per-thread gather of 4 starts (once per block lifetime) ----
    int4 st = make_int4(B, B, B, B);       // inactive threads: fully masked
    if (active) {
        int4 idx4 = indexes4[c4];
        st.x = __ldg(&starts[idx4.x]);
        st.y = __ldg(&starts[idx4.y]);
        st.z = __ldg(&starts[idx4.z]);
        st.w = __ldg(&starts[idx4.w]);
    }

    // ---- count partials (row-group 0 only; per-stripe) ----
    if (by == 0) {
        long long lc = 0;
        if (active) {
            lc  = (long long)max(B - st.x, 0);
            lc += (long long)max(B - st.y, 0);
            lc += (long long)max(B - st.z, 0);
            lc += (long long)max(B - st.w, 0);
        }
        for (int off = 16; off > 0; off >>= 1)
            lc += __shfl_down_sync(0xFFFFFFFF, lc, off);
        if (lane == 0) shc[wid] = lc;
        __syncthreads();
        if (wid == 0) {
            long long v = (lane < nwarps) ? shc[lane] : 0;
            for (int off = 16; off > 0; off >>= 1)
                v += __shfl_down_sync(0xFFFFFFFF, v, off);
            if (lane == 0) g_count_part[bx] = v;
        }
    }

    // ---- masked sum of squares over this block's row range ----
    const int r0 = by * rows_per_grp;
    const int r1 = min(r0 + rows_per_grp, B);
    int minst = min(min(st.x, st.y), min(st.z, st.w));
    int r = max(r0, minst);                // rows below minst contribute 0

    float acc = 0.0f;
    if (active && r < r1) {
        const float4* pp = p + (size_t)r * S4 + c4;
        const float4* aa = a + (size_t)r * S4 + c4;
        // 4-row unrolled main body (independent loads -> high MLP)
        for (; r + 4 <= r1; r += 4) {
            float4 p0 = pp[0],      a0 = aa[0];
            float4 p1 = pp[S4],     a1 = aa[S4];
            float4 p2 = pp[2 * S4], a2 = aa[2 * S4];
            float4 p3 = pp[3 * S4], a3 = aa[3 * S4];
            pp += 4 * S4; aa += 4 * S4;

            float d;
            d = p0.x - a0.x; acc += (r + 0 >= st.x) ? d * d : 0.0f;
            d = p0.y - a0.y; acc += (r + 0 >= st.y) ? d * d : 0.0f;
            d = p0.z - a0.z; acc += (r + 0 >= st.z) ? d * d : 0.0f;
            d = p0.w - a0.w; acc += (r + 0 >= st.w) ? d * d : 0.0f;
            d = p1.x - a1.x; acc += (r + 1 >= st.x) ? d * d : 0.0f;
            d = p1.y - a1.y; acc += (r + 1 >= st.y) ? d * d : 0.0f;
            d = p1.z - a1.z; acc += (r + 1 >= st.z) ? d * d : 0.0f;
            d = p1.w - a1.w; acc += (r + 1 >= st.w) ? d * d : 0.0f;
            d = p2.x - a2.x; acc += (r + 2 >= st.x) ? d * d : 0.0f;
            d = p2.y - a2.y; acc += (r + 2 >= st.y) ? d * d : 0.0f;
            d = p2.z - a2.z; acc += (r + 2 >= st.z) ? d * d : 0.0f;
            d = p2.w - a2.w; acc += (r + 2 >= st.w) ? d * d : 0.0f;
            d = p3.x - a3.x; acc += (r + 3 >= st.x) ? d * d : 0.0f;
            d = p3.y - a3.y; acc += (r + 3 >= st.y) ? d * d : 0.0f;
            d = p3.z - a3.z; acc += (r + 3 >= st.z) ? d * d : 0.0f;
            d = p3.w - a3.w; acc += (r + 3 >= st.w) ? d * d : 0.0f;
        }
        #pragma unroll 2
        for (; r < r1; ++r) {
            float4 pv = pp[0], av = aa[0];
            pp += S4; aa += S4;
            float d;
            d = pv.x - av.x; acc += (r >= st.x) ? d * d : 0.0f;
            d = pv.y - av.y; acc += (r >= st.y) ? d * d : 0.0f;
            d = pv.z - av.z; acc += (r >= st.z) ? d * d : 0.0f;
            d = pv.w - av.w; acc += (r >= st.w) ? d * d : 0.0f;
        }
    }

    // ---- block reduce sum -> g_partials ----
    for (int off = 16; off > 0; off >>= 1)
        acc += __shfl_down_sync(0xFFFFFFFF, acc, off);
    if (lane == 0) shf[wid] = acc;
    __syncthreads();
    if (wid == 0) {
        float v = (lane < nwarps) ? shf[lane] : 0.0f;
        for (int off = 16; off > 0; off >>= 1)
            v += __shfl_down_sync(0xFFFFFFFF, v, off);
        if (lane == 0)
            g_partials[by * gridDim.x + bx] = (double)v;
    }

    // ---- last-block finalize (atomicInc wraps to 0 -> replay-safe) ----
    __shared__ bool is_last;
    __threadfence();
    if (tid == 0) {
        unsigned int total = gridDim.x * gridDim.y;
        is_last = (atomicInc(&g_done, total - 1) == total - 1);
    }
    __syncthreads();
    if (is_last) {
        __shared__ double    shs2[TPB / 32];
        __shared__ long long shc2[TPB / 32];
        int nP = gridDim.x * gridDim.y;
        double    s = 0.0;
        long long c = 0;
        for (int i = tid; i < nP; i += TPB)
            s += *((volatile double*)&g_partials[i]);
        for (int i = tid; i < (int)gridDim.x; i += TPB)
            c += *((volatile long long*)&g_count_part[i]);
        for (int off = 16; off > 0; off >>= 1) {
            s += __shfl_down_sync(0xFFFFFFFF, s, off);
            c += __shfl_down_sync(0xFFFFFFFF, c, off);
        }
        if (lane == 0) { shs2[wid] = s; shc2[wid] = c; }
        __syncthreads();
        if (wid == 0) {
            double    vs = (lane < nwarps) ? shs2[lane] : 0.0;
            long long vc = (lane < nwarps) ? shc2[lane] : 0;
            for (int off = 16; off > 0; off >>= 1) {
                vs += __shfl_down_sync(0xFFFFFFFF, vs, off);
                vc += __shfl_down_sync(0xFFFFFFFF, vc, off);
            }
            if (lane == 0)
                out[0] = (float)sqrt(vs / (double)vc);
        }
    }
}

extern "C" void kernel_launch(void* const* d_in, const int* in_sizes, int n_in,
                              void* d_out, int out_size)
{
    const float* predictions = (const float*)d_in[0];
    const float* actuals     = (const float*)d_in[1];
    const int*   indexes     = (const int*)d_in[2];
    const int*   starts      = (const int*)d_in[3];
    float*       out         = (float*)d_out;

    int n = in_sizes[0];          // B * S
    int S = in_sizes[2];          // 16384
    int B = n / S;                // 1941
    int S4 = S / 4;               // 4096 (S % 4 == 0 for this dataset)

    int stripes = (S4 + TPB - 1) / TPB;          // 16
    if (stripes > MAX_STRIPE) stripes = MAX_STRIPE;
    int row_groups = ROW_GROUPS;                 // 18 -> 288 blocks
    while (stripes * row_groups > MAX_PART && row_groups > 1) row_groups--;
    int rows_per_grp = (B + row_groups - 1) / row_groups;

    dim3 grid(stripes, row_groups);
    fused_rmse_kernel<<<grid, TPB>>>((const float4*)predictions,
                                     (const float4*)actuals,
                                     (const int4*)indexes,
                                     starts, out, B, S4, rows_per_grp);
}

// round 8
// speedup vs baseline: 1.2138x; 1.2138x over previous
#include <cuda_runtime.h>
#include <cuda_bf16.h>
#include <math.h>

// Inputs (metadata order):
//   d_in[0] predictions  float32 [B*S]  (B=1941, S=16384), row-major [B][S]
//   d_in[1] actuals      float32 [B*S]
//   d_in[2] indexes      int32   [S]
//   d_in[3] starts       int32   [N_SERIES=30490]
// Output: float32 scalar  sqrt( sum_{j,i: j>=starts[indexes[i]]} (p[j,i]-a[j,i])^2 / count )
//
// Two launches:
//   1) fused main kernel: grid (stripes=16, row_groups=74) = 1184 blocks
//      (8 blocks/SM -> full occupancy). Thread <-> fixed column-quad; gathers
//      its 4 starts (L2-resident after wave 1), streams ~27 rows 4-row
//      unrolled, block-reduces into g_partials. Row-group 0 also writes
//      per-stripe count partials.
//   2) finalize kernel: reduce partials + counts, sqrt, write out.

#define TPB        256
#define ROW_GROUPS 74
#define MAX_PART   4096
#define MAX_STRIPE 256

__device__ double    g_partials[MAX_PART];
__device__ long long g_count_part[MAX_STRIPE];

__global__ __launch_bounds__(TPB, 8)
void fused_main_kernel(const float4* __restrict__ p,
                       const float4* __restrict__ a,
                       const int4*   __restrict__ indexes4,
                       const int*    __restrict__ starts,
                       int B, int S4, int rows_per_grp)
{
    const int bx  = blockIdx.x;
    const int by  = blockIdx.y;
    const int tid = threadIdx.x;
    const int c4  = bx * TPB + tid;        // this thread's column-quad
    const bool active = (c4 < S4);

    __shared__ float     shf[TPB / 32];
    __shared__ long long shc[TPB / 32];
    const int lane = tid & 31, wid = tid >> 5, nwarps = TPB >> 5;

    // ---- per-thread gather of 4 starts ----
    int4 st = make_int4(B, B, B, B);       // inactive threads: fully masked
    if (active) {
        int4 idx4 = indexes4[c4];
        st.x = __ldg(&starts[idx4.x]);
        st.y = __ldg(&starts[idx4.y]);
        st.z = __ldg(&starts[idx4.z]);
        st.w = __ldg(&starts[idx4.w]);
    }

    // ---- count partials (row-group 0 only; per-stripe) ----
    if (by == 0) {
        long long lc = 0;
        if (active) {
            lc  = (long long)max(B - st.x, 0);
            lc += (long long)max(B - st.y, 0);
            lc += (long long)max(B - st.z, 0);
            lc += (long long)max(B - st.w, 0);
        }
        for (int off = 16; off > 0; off >>= 1)
            lc += __shfl_down_sync(0xFFFFFFFF, lc, off);
        if (lane == 0) shc[wid] = lc;
        __syncthreads();
        if (wid == 0) {
            long long v = (lane < nwarps) ? shc[lane] : 0;
            for (int off = 16; off > 0; off >>= 1)
                v += __shfl_down_sync(0xFFFFFFFF, v, off);
            if (lane == 0) g_count_part[bx] = v;
        }
    }

    // ---- masked sum of squares over this block's row range ----
    const int r0 = by * rows_per_grp;
    const int r1 = min(r0 + rows_per_grp, B);
    int minst = min(min(st.x, st.y), min(st.z, st.w));
    int r = max(r0, minst);                // rows below minst contribute 0

    float acc = 0.0f;
    if (active && r < r1) {
        const float4* pp = p + (size_t)r * S4 + c4;
        const float4* aa = a + (size_t)r * S4 + c4;
        // 4-row unrolled main body (8 independent 16B loads in flight)
        for (; r + 4 <= r1; r += 4) {
            float4 p0 = pp[0],      a0 = aa[0];
            float4 p1 = pp[S4],     a1 = aa[S4];
            float4 p2 = pp[2 * S4], a2 = aa[2 * S4];
            float4 p3 = pp[3 * S4], a3 = aa[3 * S4];
            pp += 4 * S4; aa += 4 * S4;

            float d;
            d = p0.x - a0.x; acc += (r + 0 >= st.x) ? d * d : 0.0f;
            d = p0.y - a0.y; acc += (r + 0 >= st.y) ? d * d : 0.0f;
            d = p0.z - a0.z; acc += (r + 0 >= st.z) ? d * d : 0.0f;
            d = p0.w - a0.w; acc += (r + 0 >= st.w) ? d * d : 0.0f;
            d = p1.x - a1.x; acc += (r + 1 >= st.x) ? d * d : 0.0f;
            d = p1.y - a1.y; acc += (r + 1 >= st.y) ? d * d : 0.0f;
            d = p1.z - a1.z; acc += (r + 1 >= st.z) ? d * d : 0.0f;
            d = p1.w - a1.w; acc += (r + 1 >= st.w) ? d * d : 0.0f;
            d = p2.x - a2.x; acc += (r + 2 >= st.x) ? d * d : 0.0f;
            d = p2.y - a2.y; acc += (r + 2 >= st.y) ? d * d : 0.0f;
            d = p2.z - a2.z; acc += (r + 2 >= st.z) ? d * d : 0.0f;
            d = p2.w - a2.w; acc += (r + 2 >= st.w) ? d * d : 0.0f;
            d = p3.x - a3.x; acc += (r + 3 >= st.x) ? d * d : 0.0f;
            d = p3.y - a3.y; acc += (r + 3 >= st.y) ? d * d : 0.0f;
            d = p3.z - a3.z; acc += (r + 3 >= st.z) ? d * d : 0.0f;
            d = p3.w - a3.w; acc += (r + 3 >= st.w) ? d * d : 0.0f;
        }
        for (; r < r1; ++r) {
            float4 pv = pp[0], av = aa[0];
            pp += S4; aa += S4;
            float d;
            d = pv.x - av.x; acc += (r >= st.x) ? d * d : 0.0f;
            d = pv.y - av.y; acc += (r >= st.y) ? d * d : 0.0f;
            d = pv.z - av.z; acc += (r >= st.z) ? d * d : 0.0f;
            d = pv.w - av.w; acc += (r >= st.w) ? d * d : 0.0f;
        }
    }

    // ---- block reduce sum -> g_partials ----
    for (int off = 16; off > 0; off >>= 1)
        acc += __shfl_down_sync(0xFFFFFFFF, acc, off);
    if (lane == 0) shf[wid] = acc;
    __syncthreads();
    if (wid == 0) {
        float v = (lane < nwarps) ? shf[lane] : 0.0f;
        for (int off = 16; off > 0; off >>= 1)
            v += __shfl_down_sync(0xFFFFFFFF, v, off);
        if (lane == 0)
            g_partials[by * gridDim.x + bx] = (double)v;
    }
}

__global__ __launch_bounds__(1024)
void finalize_kernel(float* __restrict__ out, int n_part, int n_stripe)
{
    __shared__ double    shs[32];
    __shared__ long long shc[32];

    double    s = 0.0;
    long long c = 0;
    for (int i = threadIdx.x; i < n_part; i += blockDim.x)
        s += g_partials[i];
    for (int i = threadIdx.x; i < n_stripe; i += blockDim.x)
        c += g_count_part[i];

    for (int off = 16; off > 0; off >>= 1) {
        s += __shfl_down_sync(0xFFFFFFFF, s, off);
        c += __shfl_down_sync(0xFFFFFFFF, c, off);
    }
    int lane = threadIdx.x & 31, wid = threadIdx.x >> 5;
    if (lane == 0) { shs[wid] = s; shc[wid] = c; }
    __syncthreads();
    if (wid == 0) {
        int nwarps = blockDim.x >> 5;
        double    vs = (lane < nwarps) ? shs[lane] : 0.0;
        long long vc = (lane < nwarps) ? shc[lane] : 0;
        for (int off = 16; off > 0; off >>= 1) {
            vs += __shfl_down_sync(0xFFFFFFFF, vs, off);
            vc += __shfl_down_sync(0xFFFFFFFF, vc, off);
        }
        if (lane == 0)
            out[0] = (float)sqrt(vs / (double)vc);
    }
}

extern "C" void kernel_launch(void* const* d_in, const int* in_sizes, int n_in,
                              void* d_out, int out_size)
{
    const float* predictions = (const float*)d_in[0];
    const float* actuals     = (const float*)d_in[1];
    const int*   indexes     = (const int*)d_in[2];
    const int*   starts      = (const int*)d_in[3];
    float*       out         = (float*)d_out;

    int n = in_sizes[0];          // B * S
    int S = in_sizes[2];          // 16384
    int B = n / S;                // 1941
    int S4 = S / 4;               // 4096 (S % 4 == 0 for this dataset)

    int stripes = (S4 + TPB - 1) / TPB;          // 16
    if (stripes > MAX_STRIPE) stripes = MAX_STRIPE;
    int row_groups = ROW_GROUPS;                 // 74 -> 1184 blocks
    while (stripes * row_groups > MAX_PART && row_groups > 1) row_groups--;
    if (row_groups > B) row_groups = B;
    int rows_per_grp = (B + row_groups - 1) / row_groups;

    dim3 grid(stripes, row_groups);
    fused_main_kernel<<<grid, TPB>>>((const float4*)predictions,
                                     (const float4*)actuals,
                                     (const int4*)indexes,
                                     starts, B, S4, rows_per_grp);

    finalize_kernel<<<1, 1024>>>(out, stripes * row_groups, stripes);
}